// round 4
// baseline (speedup 1.0000x reference)
#include <cuda_runtime.h>

#define NN 100000
#define EE 1600000
#define HH 8
#define CH 64
#define HC 512
#define GG 64
#define OUTC 10
#define NEG 0.2f
#define NB 98   // ceil(NN/1024)

// ---------------- scratch (device globals; no runtime allocation) ----------
// NOTE: these are ONLY referenced from device code. Passing a __device__
// symbol as a kernel argument from host code silently binds the host shadow
// variable (ATS-coherent on GB300 -> reads zeros, no fault). That was the
// Round-1/2 rel_err=1.0 bug.
__device__ float g_bufA[(size_t)NN * HC];   // h (projected features)
__device__ float g_bufB[(size_t)NN * HC];   // layer outputs x1 / x2
__device__ float g_als[NN * HH];
__device__ float g_ald[NN * HH];
__device__ float g_den[NN * HH];
__device__ int   g_deg[NN];
__device__ int   g_cnt[NN];
__device__ int   g_rowptr[NN + 1];
__device__ int   g_csrc[EE];
__device__ float g_pool[GG * HC];
__device__ float g_pcnt[GG];
__device__ int   g_bsum[NB];
__device__ int   g_boff[NB];

__device__ __forceinline__ float lrelu(float x) { return x > 0.f ? x : NEG * x; }
__device__ __forceinline__ float elu1(float x)  { return x > 0.f ? x : expm1f(x); }

// ---------------- init: zero accumulators --------------------------------
__global__ void init_kernel() {
    int i = blockIdx.x * blockDim.x + threadIdx.x;
    if (i < NN) { g_deg[i] = 0; g_cnt[i] = 0; }
    if (i < GG * HC) g_pool[i] = 0.f;
    if (i < GG) g_pcnt[i] = 0.f;
}

// ---------------- CSR build ------------------------------------------------
__global__ void count_kernel(const int* __restrict__ ei) {
    int e = blockIdx.x * blockDim.x + threadIdx.x;
    if (e >= EE) return;
    atomicAdd(&g_deg[ei[EE + e]], 1);   // dst
}

__global__ void scan1_kernel() {
    __shared__ int sh[1024];
    int tid = threadIdx.x;
    int i = blockIdx.x * 1024 + tid;
    int v = (i < NN) ? g_deg[i] : 0;
    sh[tid] = v;
    __syncthreads();
    for (int off = 1; off < 1024; off <<= 1) {
        int t = (tid >= off) ? sh[tid - off] : 0;
        __syncthreads();
        sh[tid] += t;
        __syncthreads();
    }
    if (i < NN) g_rowptr[i] = sh[tid] - v;            // exclusive within block
    if (tid == 1023) g_bsum[blockIdx.x] = sh[1023];
}

__global__ void scan2_kernel() {
    int run = 0;
    for (int b = 0; b < NB; b++) { g_boff[b] = run; run += g_bsum[b]; }
}

__global__ void scan3_kernel() {
    int i = blockIdx.x * blockDim.x + threadIdx.x;
    if (i < NN) g_rowptr[i] += g_boff[i >> 10];
    if (i == 0) g_rowptr[NN] = EE;
}

__global__ void scatter_kernel(const int* __restrict__ ei) {
    int e = blockIdx.x * blockDim.x + threadIdx.x;
    if (e >= EE) return;
    int s = ei[e];
    int d = ei[EE + e];
    int pos = g_rowptr[d] + atomicAdd(&g_cnt[d], 1);
    g_csrc[pos] = s;
}

// ---------------- layer-1 projection (K=3) + attention logits -------------
// block = 128 threads = one node; thread t owns channels [4t, 4t+4)
// writes h -> g_bufA, logits -> g_als/g_ald
__global__ void proj1_al_kernel(const float* __restrict__ x,
                                const float* __restrict__ W1,
                                const float* __restrict__ a_s,
                                const float* __restrict__ a_d) {
    int n = blockIdx.x;
    int tid = threadIdx.x;
    float x0 = x[n * 3 + 0], x1 = x[n * 3 + 1], x2 = x[n * 3 + 2];
    int c4 = tid * 4;
    float4 w0 = *(const float4*)(W1 + 0 * HC + c4);
    float4 w1 = *(const float4*)(W1 + 1 * HC + c4);
    float4 w2 = *(const float4*)(W1 + 2 * HC + c4);
    float4 h;
    h.x = x0 * w0.x + x1 * w1.x + x2 * w2.x;
    h.y = x0 * w0.y + x1 * w1.y + x2 * w2.y;
    h.z = x0 * w0.z + x1 * w1.z + x2 * w2.z;
    h.w = x0 * w0.w + x1 * w1.w + x2 * w2.w;
    *(float4*)(g_bufA + (size_t)n * HC + c4) = h;

    int head = tid >> 4;
    int cc = (tid & 15) * 4;                       // within-head channel
    float4 as4 = *(const float4*)(a_s + head * CH + cc);
    float4 ad4 = *(const float4*)(a_d + head * CH + cc);
    float ps = h.x * as4.x + h.y * as4.y + h.z * as4.z + h.w * as4.w;
    float pd = h.x * ad4.x + h.y * ad4.y + h.z * ad4.z + h.w * ad4.w;
#pragma unroll
    for (int o = 8; o > 0; o >>= 1) {
        ps += __shfl_xor_sync(0xffffffffu, ps, o, 16);
        pd += __shfl_xor_sync(0xffffffffu, pd, o, 16);
    }
    if ((tid & 15) == 0) {
        g_als[n * HH + head] = ps;
        g_ald[n * HH + head] = pd;
    }
}

// ---------------- attention logits from g_bufA (layer 2) ------------------
__global__ void al_kernel(const float* __restrict__ a_s,
                          const float* __restrict__ a_d) {
    int n = blockIdx.x;
    int tid = threadIdx.x;
    int c4 = tid * 4;
    float4 h = *(const float4*)(g_bufA + (size_t)n * HC + c4);
    int head = tid >> 4;
    int cc = (tid & 15) * 4;
    float4 as4 = *(const float4*)(a_s + head * CH + cc);
    float4 ad4 = *(const float4*)(a_d + head * CH + cc);
    float ps = h.x * as4.x + h.y * as4.y + h.z * as4.z + h.w * as4.w;
    float pd = h.x * ad4.x + h.y * ad4.y + h.z * ad4.z + h.w * ad4.w;
#pragma unroll
    for (int o = 8; o > 0; o >>= 1) {
        ps += __shfl_xor_sync(0xffffffffu, ps, o, 16);
        pd += __shfl_xor_sync(0xffffffffu, pd, o, 16);
    }
    if ((tid & 15) == 0) {
        g_als[n * HH + head] = ps;
        g_ald[n * HH + head] = pd;
    }
}

// ---------------- softmax denominator: self-loop init ---------------------
__global__ void den_self_kernel() {
    int n = blockIdx.x * blockDim.x + threadIdx.x;
    if (n >= NN) return;
#pragma unroll
    for (int h = 0; h < HH; h++) {
        float t = g_als[n * HH + h] + g_ald[n * HH + h];
        g_den[n * HH + h] = expf(lrelu(t));
    }
}

// ---------------- softmax denominator: edges ------------------------------
__global__ void den_edge_kernel(const int* __restrict__ ei) {
    int e = blockIdx.x * blockDim.x + threadIdx.x;
    if (e >= EE) return;
    int s = ei[e];
    int d = ei[EE + e];
    float4 as0 = *(const float4*)&g_als[s * HH];
    float4 as1 = *(const float4*)&g_als[s * HH + 4];
    float4 ad0 = *(const float4*)&g_ald[d * HH];
    float4 ad1 = *(const float4*)&g_ald[d * HH + 4];
    float sv[8] = {as0.x, as0.y, as0.z, as0.w, as1.x, as1.y, as1.z, as1.w};
    float dv[8] = {ad0.x, ad0.y, ad0.z, ad0.w, ad1.x, ad1.y, ad1.z, ad1.w};
#pragma unroll
    for (int h = 0; h < HH; h++) {
        float w = expf(lrelu(sv[h] + dv[h]));
        atomicAdd(&g_den[d * HH + h], w);
    }
}

// ---------------- aggregation: block = one dst node -----------------------
// reads h from g_bufA, writes elu(out)+bias to g_bufB (fixed dataflow, both layers)
__global__ void agg_kernel(const float* __restrict__ bias) {
    int n = blockIdx.x;
    int tid = threadIdx.x;          // 0..127
    int head = tid >> 4;
    int myc = tid * 4;
    float ald_n = g_ald[n * HH + head];
    float als_base_n = g_als[n * HH + head];

    float4 acc = make_float4(0.f, 0.f, 0.f, 0.f);
    int beg = g_rowptr[n], end = g_rowptr[n + 1];
    for (int j = beg - 1; j < end; j++) {          // j<beg -> self loop
        int s = (j < beg) ? n : g_csrc[j];
        float w = 0.f;
        if ((tid & 15) == 0) {                     // one exp per 16-lane segment
            float logit = ((j < beg) ? als_base_n : g_als[s * HH + head]) + ald_n;
            w = expf(lrelu(logit));
        }
        w = __shfl_sync(0xffffffffu, w, (tid & 16), 32);
        float4 hv = *(const float4*)(g_bufA + (size_t)s * HC + myc);
        acc.x += w * hv.x; acc.y += w * hv.y;
        acc.z += w * hv.z; acc.w += w * hv.w;
    }
    float inv = 1.f / g_den[n * HH + head];
    float4 b4 = *(const float4*)(bias + myc);
    float4 o;
    o.x = elu1(acc.x * inv + b4.x);
    o.y = elu1(acc.y * inv + b4.y);
    o.z = elu1(acc.z * inv + b4.z);
    o.w = elu1(acc.w * inv + b4.w);
    *(float4*)(g_bufB + (size_t)n * HC + myc) = o;
}

// ---------------- 128x128x8 fp32 SGEMM: g_bufA = g_bufB @ W ----------------
__global__ __launch_bounds__(256) void sgemm512(const float* __restrict__ W) {
    __shared__ float As[8][132];
    __shared__ float Bs[8][132];
    const float* A = g_bufB;
    float* Cout = g_bufA;
    const int M = NN;
    int tid = threadIdx.x;
    int bm = blockIdx.x * 128;
    int bn = blockIdx.y * 128;
    int ar = tid >> 1;
    int ak = (tid & 1) << 2;
    int brow = tid >> 5;
    int bcol = (tid & 31) << 2;
    int ty = tid >> 4, tx = tid & 15;
    float acc[8][8];
#pragma unroll
    for (int i = 0; i < 8; i++)
#pragma unroll
        for (int j = 0; j < 8; j++) acc[i][j] = 0.f;

    int arow = bm + ar;
    bool avld = arow < M;
    const float* Ap = A + (size_t)arow * 512 + ak;

    for (int k0 = 0; k0 < 512; k0 += 8) {
        float4 a4 = avld ? *(const float4*)(Ap + k0) : make_float4(0.f, 0.f, 0.f, 0.f);
        As[ak + 0][ar] = a4.x; As[ak + 1][ar] = a4.y;
        As[ak + 2][ar] = a4.z; As[ak + 3][ar] = a4.w;
        float4 b4 = *(const float4*)(W + (size_t)(k0 + brow) * 512 + bn + bcol);
        *(float4*)&Bs[brow][bcol] = b4;
        __syncthreads();
#pragma unroll
        for (int k = 0; k < 8; k++) {
            float a[8], b[8];
            float4 t;
            t = *(const float4*)&As[k][ty * 8];     a[0]=t.x; a[1]=t.y; a[2]=t.z; a[3]=t.w;
            t = *(const float4*)&As[k][ty * 8 + 4]; a[4]=t.x; a[5]=t.y; a[6]=t.z; a[7]=t.w;
            t = *(const float4*)&Bs[k][tx * 8];     b[0]=t.x; b[1]=t.y; b[2]=t.z; b[3]=t.w;
            t = *(const float4*)&Bs[k][tx * 8 + 4]; b[4]=t.x; b[5]=t.y; b[6]=t.z; b[7]=t.w;
#pragma unroll
            for (int i = 0; i < 8; i++)
#pragma unroll
                for (int j = 0; j < 8; j++)
                    acc[i][j] += a[i] * b[j];
        }
        __syncthreads();
    }
#pragma unroll
    for (int i = 0; i < 8; i++) {
        int row = bm + ty * 8 + i;
        if (row < M) {
            *(float4*)(Cout + (size_t)row * 512 + bn + tx * 8) =
                make_float4(acc[i][0], acc[i][1], acc[i][2], acc[i][3]);
            *(float4*)(Cout + (size_t)row * 512 + bn + tx * 8 + 4) =
                make_float4(acc[i][4], acc[i][5], acc[i][6], acc[i][7]);
        }
    }
}

// ---------------- global mean pool (atomic) -------------------------------
__global__ void pool_kernel(const int* __restrict__ batch) {
    int n = blockIdx.x;
    int tid = threadIdx.x;
    int g = batch[n];
    float4 v = *(const float4*)(g_bufB + (size_t)n * HC + tid * 4);
    atomicAdd(&g_pool[g * HC + tid * 4 + 0], v.x);
    atomicAdd(&g_pool[g * HC + tid * 4 + 1], v.y);
    atomicAdd(&g_pool[g * HC + tid * 4 + 2], v.z);
    atomicAdd(&g_pool[g * HC + tid * 4 + 3], v.w);
    if (tid == 0) atomicAdd(&g_pcnt[g], 1.f);
}

// ---------------- classifier ----------------------------------------------
__global__ void cls_kernel(const float* __restrict__ Wc,
                           const float* __restrict__ bc,
                           float* __restrict__ out) {
    __shared__ float row[HC];
    int g = blockIdx.x;
    int tid = threadIdx.x;
    float inv = 1.f / fmaxf(g_pcnt[g], 1.f);
    for (int i = tid; i < HC; i += blockDim.x) row[i] = g_pool[g * HC + i] * inv;
    __syncthreads();
    if (tid < OUTC) {
        float s = bc[tid];
        for (int k = 0; k < HC; k++) s += row[k] * Wc[k * OUTC + tid];
        out[g * OUTC + tid] = s;
    }
}

// ---------------- launch ---------------------------------------------------
extern "C" void kernel_launch(void* const* d_in, const int* in_sizes, int n_in,
                              void* d_out, int out_size) {
    const float* x    = (const float*)d_in[0];
    const int*   ei   = (const int*)  d_in[1];
    const int*   batch= (const int*)  d_in[2];
    const float* W1   = (const float*)d_in[3];
    const float* a1s  = (const float*)d_in[4];
    const float* a1d  = (const float*)d_in[5];
    const float* b1   = (const float*)d_in[6];
    const float* W2   = (const float*)d_in[7];
    const float* a2s  = (const float*)d_in[8];
    const float* a2d  = (const float*)d_in[9];
    const float* b2   = (const float*)d_in[10];
    const float* Wc   = (const float*)d_in[11];
    const float* bc   = (const float*)d_in[12];
    float* out = (float*)d_out;

    const int gN  = (NN + 255) / 256;
    const int gE  = (EE + 255) / 256;

    init_kernel<<<gN, 256>>>();
    // CSR build (shared by both layers)
    count_kernel<<<gE, 256>>>(ei);
    scan1_kernel<<<NB, 1024>>>();
    scan2_kernel<<<1, 1>>>();
    scan3_kernel<<<gN, 256>>>();
    scatter_kernel<<<gE, 256>>>(ei);

    // ---- layer 1 ----
    proj1_al_kernel<<<NN, 128>>>(x, W1, a1s, a1d);   // h1 -> bufA
    den_self_kernel<<<gN, 256>>>();
    den_edge_kernel<<<gE, 256>>>(ei);
    agg_kernel<<<NN, 128>>>(b1);                     // bufA -> x1 in bufB

    // ---- layer 2 ----
    {
        dim3 grid((NN + 127) / 128, 4);
        sgemm512<<<grid, 256>>>(W2);                 // bufB @ W2 -> h2 in bufA
    }
    al_kernel<<<NN, 128>>>(a2s, a2d);
    den_self_kernel<<<gN, 256>>>();
    den_edge_kernel<<<gE, 256>>>(ei);
    agg_kernel<<<NN, 128>>>(b2);                     // bufA -> x2 in bufB

    // ---- readout ----
    pool_kernel<<<NN, 128>>>(batch);
    cls_kernel<<<GG, 128>>>(Wc, bc, out);
}